// round 5
// baseline (speedup 1.0000x reference)
#include <cuda_runtime.h>
#include <cuda_pipeline.h>

#define Bx 4
#define Nn 2048
#define Dd 512
#define Hh 8
#define NCH 32      // chunks of 64 node rows
#define ROWS 64
#define SUB 16
#define NSUB 4
#define GRID 128
#define NTHR 512

// ---------------- device scratch ----------------
__device__ float g_u[Hh][Dd];
__device__ float g_ch[Hh];
__device__ float g_s0p[Hh][8];
__device__ float g_pm[Bx][NCH][Hh];
__device__ float g_ps[Bx][NCH][Hh];
__device__ float g_zp[NCH][Bx][Hh][Dd];
__device__ float g_w[Bx][Dd];
__device__ float g_y[Bx][Dd];
__device__ unsigned g_start = 0;      // monotonic across replays
__device__ unsigned g_bar[4] = {0, 0, 0, 0};

__device__ __forceinline__ float warp_sum(float v) {
    #pragma unroll
    for (int o = 16; o; o >>= 1) v += __shfl_xor_sync(0xffffffffu, v, o);
    return v;
}
__device__ __forceinline__ float warp_max(float v) {
    #pragma unroll
    for (int o = 16; o; o >>= 1) v = fmaxf(v, __shfl_xor_sync(0xffffffffu, v, o));
    return v;
}
__device__ __forceinline__ float dot4(float4 a, float4 b) {
    return a.x * b.x + a.y * b.y + a.z * b.z + a.w * b.w;
}

// grid barrier: monotonic counter, target = 128 * replay_epoch
#define GBAR(i)                                                   \
    do {                                                          \
        __syncthreads();                                          \
        if (t == 0) {                                             \
            __threadfence();                                      \
            atomicAdd(&g_bar[i], 1u);                             \
            while (*(volatile unsigned*)&g_bar[i] < target) { }   \
            __threadfence();                                      \
        }                                                         \
        __syncthreads();                                          \
    } while (0)

__global__ void __launch_bounds__(NTHR, 1)
k_fused(const float* __restrict__ nf, const float* __restrict__ masks,
        const float* __restrict__ ct,
        const float* __restrict__ Wq, const float* __restrict__ bq,
        const float* __restrict__ Wk, const float* __restrict__ bk,
        const float* __restrict__ Wv, const float* __restrict__ bv,
        const float* __restrict__ Wo, const float* __restrict__ bo,
        const float* __restrict__ gamma, const float* __restrict__ beta,
        float* __restrict__ out) {
    extern __shared__ __align__(16) float dyn[];   // 128 KB: 4 subtiles of 16x512
    __shared__ __align__(16) float cts[Dd];
    __shared__ float q0s[64], red8[8][64], red64[64];
    __shared__ __align__(16) float us[Hh][Dd];
    __shared__ float sc[Hh][SUB], es[Hh][SUB];
    __shared__ float mh[Hh], sh[Hh], alpha[Hh], chs[Hh], msk[ROWS];
    __shared__ float fC[NCH], f0sh;
    __shared__ __align__(16) float zs[Dd];
    __shared__ __align__(16) float ws[Bx][Dd];
    __shared__ float part[4][4][Bx];
    __shared__ float red[NTHR];
    __shared__ unsigned s_target;

    const int bid = blockIdx.x;
    const int t = threadIdx.x, wid = t >> 5, lane = t & 31;

    // ---- replay epoch ----
    if (t == 0) s_target = ((atomicAdd(&g_start, 1u) >> 7) + 1u) * GRID;
    const int cB = bid >> 2, bB = bid & 3;   // phase-B task (chunk, batch)

    // ---- issue nf prefetch for phase B immediately (overlaps phase A) ----
    #pragma unroll
    for (int st = 0; st < NSUB; st++) {
        const float4* src = (const float4*)(nf + ((size_t)bB * Nn + cB * ROWS + st * SUB) * Dd);
        float4* dst = (float4*)(dyn + st * SUB * Dd);
        #pragma unroll
        for (int k = 0; k < 4; k++)
            __pipeline_memcpy_async(&dst[t + k * 512], &src[t + k * 512], 16);
        __pipeline_commit();
    }
    if (t < ROWS) msk[t] = masks[(size_t)bB * Nn + cB * ROWS + t];

    // ================= Phase A: prep (blocks 0..63) =================
    if (bid < 64) {
        const int h = bid >> 3, dc = bid & 7;
        cts[t] = ct[t];
        __syncthreads();
        {   // q0 slice for head h: 16 warps x 4 rows
            const float4* cv = (const float4*)cts;
            #pragma unroll
            for (int rr = 0; rr < 4; rr++) {
                const int i = wid + rr * 16;
                const float4* row = (const float4*)(Wq + (size_t)(h * 64 + i) * Dd);
                float s = 0.f;
                #pragma unroll
                for (int k = 0; k < 4; k++) s += dot4(row[lane + 32 * k], cv[lane + 32 * k]);
                s = warp_sum(s);
                if (lane == 0) q0s[i] = s + bq[h * 64 + i];
            }
        }
        __syncthreads();
        const int part8 = t >> 6, dl = t & 63;
        {
            const float* base = Wk + (size_t)(h * 64 + part8 * 8) * Dd + dc * 64 + dl;
            float acc = 0.f;
            #pragma unroll
            for (int i = 0; i < 8; i++) acc += q0s[part8 * 8 + i] * base[(size_t)i * Dd];
            red8[part8][dl] = acc;
        }
        __syncthreads();
        if (t < 64) {
            float u = 0.f;
            #pragma unroll
            for (int p = 0; p < 8; p++) u += red8[p][t];
            g_u[h][dc * 64 + t] = u;
            red64[t] = u * cts[dc * 64 + t];
        }
        __syncthreads();
        if (t < 32) {
            float v = red64[t] + red64[t + 32];
            v = warp_sum(v);
            if (t == 0) g_s0p[h][dc] = v;
            if (dc == 0) {
                float cvv = q0s[t] * bk[h * 64 + t] + q0s[t + 32] * bk[h * 64 + t + 32];
                cvv = warp_sum(cvv);
                if (t == 0) g_ch[h] = cvv;
            }
        }
    }
    __syncthreads();
    const unsigned target = s_target;
    GBAR(0);

    // ================= Phase B: flash pass (all 128 blocks) =================
    {
        if (t < Hh) { mh[t] = -3e38f; sh[t] = 0.f; chs[t] = g_ch[t]; }
        const float* uf = &g_u[0][0];
        #pragma unroll
        for (int k = 0; k < 8; k++) us[0][t + k * 512] = uf[t + k * 512];

        float z[Hh];
        #pragma unroll
        for (int h = 0; h < Hh; h++) z[h] = 0.f;

        #pragma unroll
        for (int st = 0; st < NSUB; st++) {
            __pipeline_wait_prior(NSUB - 1 - st);
            __syncthreads();
            const float* xt = dyn + st * SUB * Dd;
            {   // scores: warp w -> head w>>1, rows (w&1)*8..+8
                const int h = wid >> 1, r0 = (wid & 1) * 8;
                const float4* uf4 = (const float4*)us[h];
                #pragma unroll
                for (int rr = 0; rr < 8; rr++) {
                    const int r = r0 + rr;
                    const float4* xf4 = (const float4*)(xt + r * Dd);
                    float s = 0.f;
                    #pragma unroll
                    for (int k = 0; k < 4; k++) s += dot4(uf4[lane + 32 * k], xf4[lane + 32 * k]);
                    s = warp_sum(s);
                    if (lane == 0) {
                        float mv = msk[st * SUB + r];
                        float v = (s + chs[h]) * 0.125f;
                        if (mv * mv == 0.f) v = -1e9f;
                        sc[h][r] = v;
                    }
                }
            }
            __syncthreads();
            if (wid < Hh) {   // online softmax per head
                const int h = wid;
                float v = (lane < SUB) ? sc[h][lane] : -3e38f;
                float m = warp_max(v);
                float mnew = fmaxf(mh[h], m);
                float e = (lane < SUB) ? expf(v - mnew) : 0.f;
                float ss = warp_sum(e);
                if (lane < SUB) es[h][lane] = e;
                if (lane == 0) {
                    alpha[h] = expf(mh[h] - mnew);
                    sh[h] = sh[h] * alpha[h] + ss;
                    mh[h] = mnew;
                }
            }
            __syncthreads();
            #pragma unroll
            for (int h = 0; h < Hh; h++) z[h] *= alpha[h];
            #pragma unroll 4
            for (int r = 0; r < SUB; r++) {
                const float xv = xt[r * Dd + t];
                #pragma unroll
                for (int h = 0; h < Hh; h++) z[h] += es[h][r] * xv;
            }
        }
        __syncthreads();
        #pragma unroll
        for (int h = 0; h < Hh; h++) g_zp[cB][bB][h][t] = z[h];
        if (t < Hh) { g_pm[bB][cB][t] = mh[t]; g_ps[bB][cB][t] = sh[t]; }
    }
    GBAR(1);

    // ================= Phase C: combine + Wv (blocks 0..31) =================
    if (bid < 32) {
        const int h = bid >> 2, b = bid & 3;
        if (t < 32) {
            float sp = (lane < 8) ? g_s0p[h][lane] : 0.f;
            sp = warp_sum(sp);
            const float s0 = (sp + g_ch[h]) * 0.125f;
            const float pm = g_pm[b][lane][h];
            const float M = fmaxf(warp_max(pm), s0);
            float e = g_ps[b][lane][h] * expf(pm - M);
            e = warp_sum(e);
            const float S = e + expf(s0 - M);
            fC[lane] = expf(pm - M) / S;
            if (lane == 0) f0sh = expf(s0 - M) / S;
        }
        __syncthreads();
        {
            float acc = f0sh * ct[t];
            #pragma unroll 8
            for (int c = 0; c < NCH; c++) acc += fC[c] * g_zp[c][b][h][t];
            zs[t] = acc;
        }
        __syncthreads();
        const float4* zv = (const float4*)zs;
        #pragma unroll
        for (int rr = 0; rr < 4; rr++) {
            const int i = h * 64 + wid + rr * 16;
            const float4* row = (const float4*)(Wv + (size_t)i * Dd);
            float s = 0.f;
            #pragma unroll
            for (int k = 0; k < 4; k++) s += dot4(row[lane + 32 * k], zv[lane + 32 * k]);
            s = warp_sum(s);
            if (lane == 0) g_w[b][i] = s + bv[i];
        }
    }
    GBAR(2);

    // ================= Phase D: Wo (all 128 blocks, 4 rows each) =================
    {
        #pragma unroll
        for (int idx = t; idx < Bx * Dd; idx += NTHR)
            ws[idx >> 9][idx & 511] = g_w[idx >> 9][idx & 511];
        __syncthreads();
        const int rloc = wid >> 2, q = wid & 3;
        const int r = bid * 4 + rloc;
        const float4 rv = ((const float4*)(Wo + (size_t)r * Dd))[q * 32 + lane];
        float sb[Bx];
        #pragma unroll
        for (int b = 0; b < Bx; b++) {
            sb[b] = dot4(rv, ((const float4*)ws[b])[q * 32 + lane]);
            sb[b] = warp_sum(sb[b]);
            if (lane == 0) part[rloc][q][b] = sb[b];
        }
        __syncthreads();
        if (t < 16) {
            const int rl = t >> 2, b = t & 3;
            const int rr = bid * 4 + rl;
            g_y[b][rr] = part[rl][0][b] + part[rl][1][b] + part[rl][2][b] + part[rl][3][b]
                       + bo[rr] + ct[rr];
        }
        __syncthreads();
    }

    // ================= Final: arrive; block 0 alone does LayerNorm =================
    if (bid != 0) {
        if (t == 0) { __threadfence(); atomicAdd(&g_bar[3], 1u); }
        return;
    }
    if (t == 0) {
        __threadfence();
        atomicAdd(&g_bar[3], 1u);
        while (*(volatile unsigned*)&g_bar[3] < target) { }
        __threadfence();
    }
    __syncthreads();
    for (int b = 0; b < Bx; b++) {
        const float y = g_y[b][t];
        red[t] = y; __syncthreads();
        for (int o = 256; o; o >>= 1) { if (t < o) red[t] += red[t + o]; __syncthreads(); }
        const float mu = red[0] * (1.f / Dd);
        __syncthreads();
        const float dy = y - mu;
        red[t] = dy * dy; __syncthreads();
        for (int o = 256; o; o >>= 1) { if (t < o) red[t] += red[t + o]; __syncthreads(); }
        const float rs = rsqrtf(red[0] * (1.f / Dd) + 1e-5f);
        out[(size_t)b * Dd + t] = dy * rs * gamma[t] + beta[t];
        __syncthreads();
    }
}

// ---------------- launcher ----------------
extern "C" void kernel_launch(void* const* d_in, const int* in_sizes, int n_in,
                              void* d_out, int out_size) {
    const float* nf    = (const float*)d_in[0];
    // d_in[1] edge_weights, d_in[2] adj_matrix: dead for CLS-row output
    const float* masks = (const float*)d_in[3];
    const float* ct    = (const float*)d_in[4];
    const float* Wq    = (const float*)d_in[5];
    const float* bq    = (const float*)d_in[6];
    const float* Wk    = (const float*)d_in[7];
    const float* bk    = (const float*)d_in[8];
    const float* Wv    = (const float*)d_in[9];
    const float* bv    = (const float*)d_in[10];
    const float* Wo    = (const float*)d_in[11];
    const float* bo    = (const float*)d_in[12];
    const float* gamma = (const float*)d_in[13];
    const float* beta  = (const float*)d_in[14];
    float* out = (float*)d_out;

    const int dyn = NSUB * SUB * Dd * sizeof(float);   // 128 KB
    static bool attr_set = false;
    if (!attr_set) {
        cudaFuncSetAttribute(k_fused, cudaFuncAttributeMaxDynamicSharedMemorySize, dyn);
        attr_set = true;
    }
    k_fused<<<GRID, NTHR, dyn>>>(nf, masks, ct, Wq, bq, Wk, bk, Wv, bv,
                                 Wo, bo, gamma, beta, out);
}

// round 6
// speedup vs baseline: 1.0706x; 1.0706x over previous
#include <cuda_runtime.h>

#define Bx 4
#define Nn 2048
#define Dd 512
#define Hh 8
#define ZCH 64     // z chunks
#define ZR  32     // rows per z chunk

// ---------------- device scratch ----------------
__device__ float g_u[Hh][Dd];
__device__ float g_ch[Hh];
__device__ float g_s0p[Hh][8];
__device__ float g_sc[Bx][Hh][Nn];         // node scores (node = j-1)
__device__ float g_nm[Bx][Hh];             // softmax max
__device__ float g_ns[Bx][Hh];             // softmax sum
__device__ float g_zp[ZCH][Bx][Hh][Dd];    // final-p-weighted z partials
__device__ float g_w[Bx][Dd];
__device__ float g_y[Bx][Dd];

__device__ __forceinline__ float warp_sum(float v) {
    #pragma unroll
    for (int o = 16; o; o >>= 1) v += __shfl_xor_sync(0xffffffffu, v, o);
    return v;
}
__device__ __forceinline__ float warp_max(float v) {
    #pragma unroll
    for (int o = 16; o; o >>= 1) v = fmaxf(v, __shfl_xor_sync(0xffffffffu, v, o));
    return v;
}
__device__ __forceinline__ float dot4(float4 a, float4 b) {
    return a.x * b.x + a.y * b.y + a.z * b.z + a.w * b.w;
}

// ============ k_prep: per (head, d-chunk): q0 slice, u, s0 partials, ch ============
// grid (Hh, 8), 512 threads
__global__ void k_prep(const float* __restrict__ Wq, const float* __restrict__ bq,
                       const float* __restrict__ Wk, const float* __restrict__ bk,
                       const float* __restrict__ ct) {
    const int h = blockIdx.x, dc = blockIdx.y;
    const int t = threadIdx.x, wid = t >> 5, lane = t & 31;
    __shared__ __align__(16) float cts[Dd];
    __shared__ float q0s[64], red8[8][64], red64[64];
    cts[t] = ct[t];
    __syncthreads();
    {   // q0 slice for head h: 16 warps x 4 rows
        const float4* cv = (const float4*)cts;
        #pragma unroll
        for (int rr = 0; rr < 4; rr++) {
            const int i = wid + rr * 16;
            const float4* row = (const float4*)(Wq + (size_t)(h * 64 + i) * Dd);
            float s = 0.f;
            #pragma unroll
            for (int k = 0; k < 4; k++) s += dot4(row[lane + 32 * k], cv[lane + 32 * k]);
            s = warp_sum(s);
            if (lane == 0) q0s[i] = s + bq[h * 64 + i];
        }
    }
    __syncthreads();
    const int part8 = t >> 6, dl = t & 63;
    {
        const float* base = Wk + (size_t)(h * 64 + part8 * 8) * Dd + dc * 64 + dl;
        float acc = 0.f;
        #pragma unroll
        for (int i = 0; i < 8; i++) acc += q0s[part8 * 8 + i] * base[(size_t)i * Dd];
        red8[part8][dl] = acc;
    }
    __syncthreads();
    if (t < 64) {
        float u = 0.f;
        #pragma unroll
        for (int p = 0; p < 8; p++) u += red8[p][t];
        g_u[h][dc * 64 + t] = u;
        red64[t] = u * cts[dc * 64 + t];
    }
    __syncthreads();
    if (t < 32) {
        float v = red64[t] + red64[t + 32];
        v = warp_sum(v);
        if (t == 0) g_s0p[h][dc] = v;
        if (dc == 0) {
            float cvv = q0s[t] * bk[h * 64 + t] + q0s[t + 32] * bk[h * 64 + t + 32];
            cvv = warp_sum(cvv);
            if (t == 0) g_ch[h] = cvv;
        }
    }
}

// ============ k_scores: warp = one node row, all 8 heads ============
// grid (Nn/8, Bx), 256 threads
__global__ void k_scores(const float* __restrict__ nf, const float* __restrict__ masks) {
    __shared__ __align__(16) float4 us4[Hh * 128];   // 16 KB
    __shared__ float chs[Hh];
    const int b = blockIdx.y;
    const int t = threadIdx.x, wid = t >> 5, lane = t & 31;
    {
        const float4* uf = (const float4*)&g_u[0][0];
        #pragma unroll
        for (int k = 0; k < 4; k++) us4[t + k * 256] = uf[t + k * 256];
        if (t < Hh) chs[t] = g_ch[t];
    }
    __syncthreads();
    const int node = blockIdx.x * 8 + wid;
    const float4* x4 = (const float4*)(nf + ((size_t)b * Nn + node) * Dd);
    float4 xr[4];
    #pragma unroll
    for (int k = 0; k < 4; k++) xr[k] = x4[lane + 32 * k];
    const float mv = masks[(size_t)b * Nn + node];
    #pragma unroll
    for (int h = 0; h < Hh; h++) {
        float s = 0.f;
        #pragma unroll
        for (int k = 0; k < 4; k++) s += dot4(us4[h * 128 + lane + 32 * k], xr[k]);
        s = warp_sum(s);
        if (lane == 0) {
            float v = (s + chs[h]) * 0.125f;
            if (mv * mv == 0.f) v = -1e9f;
            g_sc[b][h][node] = v;
        }
    }
}

// ============ k_softmax: per (b,h) -> (M, S) only. grid 32, 1024 thr ============
__global__ void k_softmax() {
    const int b = blockIdx.x >> 3, h = blockIdx.x & 7;
    const int t = threadIdx.x, wid = t >> 5, lane = t & 31;
    __shared__ float red[32];
    __shared__ float Msh, s0sh;
    const float v0 = g_sc[b][h][t], v1 = g_sc[b][h][t + 1024];
    float m = warp_max(fmaxf(v0, v1));
    if (lane == 0) red[wid] = m;
    __syncthreads();
    if (wid == 0) {
        float x = warp_max(red[lane]);
        if (lane == 0) {
            float sp = 0.f;
            #pragma unroll
            for (int dc = 0; dc < 8; dc++) sp += g_s0p[h][dc];
            const float s0 = (sp + g_ch[h]) * 0.125f;
            s0sh = s0;
            Msh = fmaxf(x, s0);
        }
    }
    __syncthreads();
    const float M = Msh;
    float e = expf(v0 - M) + expf(v1 - M);
    e = warp_sum(e);
    if (lane == 0) red[wid] = e;
    __syncthreads();
    if (wid == 0) {
        float x = warp_sum(red[lane]);
        if (lane == 0) {
            g_nm[b][h] = M;
            g_ns[b][h] = x + expf(s0sh - M);
        }
    }
}

// ============ k_z: final-p-weighted partial sums, direct global reads ============
// grid (ZCH, Bx), 512 threads
__global__ void k_z(const float* __restrict__ nf) {
    const int c = blockIdx.x, b = blockIdx.y;
    const int t = threadIdx.x;
    __shared__ float ps[Hh][ZR];
    if (t < Hh * ZR) {
        const int h = t >> 5, jj = t & 31;
        const float rS = 1.f / g_ns[b][h];
        ps[h][jj] = expf(g_sc[b][h][c * ZR + jj] - g_nm[b][h]) * rS;
    }
    __syncthreads();
    float acc[Hh];
    #pragma unroll
    for (int h = 0; h < Hh; h++) acc[h] = 0.f;
    const float* xp = nf + ((size_t)b * Nn + c * ZR) * Dd + t;
    #pragma unroll 4
    for (int jj = 0; jj < ZR; jj++) {
        const float xv = xp[(size_t)jj * Dd];
        #pragma unroll
        for (int h = 0; h < Hh; h++) acc[h] += ps[h][jj] * xv;
    }
    #pragma unroll
    for (int h = 0; h < Hh; h++) g_zp[c][b][h][t] = acc[h];
}

// ============ k_zv: sum chunk partials + CLS term + Wv GEMV ============
// grid (Hh, Bx), 512 threads
__global__ void k_zv(const float* __restrict__ ct, const float* __restrict__ Wv,
                     const float* __restrict__ bv) {
    const int h = blockIdx.x, b = blockIdx.y;
    const int t = threadIdx.x, wid = t >> 5, lane = t & 31;
    __shared__ __align__(16) float zs[Dd];
    __shared__ float p0sh;
    if (t == 0) {
        float sp = 0.f;
        #pragma unroll
        for (int dc = 0; dc < 8; dc++) sp += g_s0p[h][dc];
        const float s0 = (sp + g_ch[h]) * 0.125f;
        p0sh = expf(s0 - g_nm[b][h]) / g_ns[b][h];
    }
    __syncthreads();
    {
        float acc = p0sh * ct[t];
        #pragma unroll 8
        for (int c = 0; c < ZCH; c++) acc += g_zp[c][b][h][t];
        zs[t] = acc;
    }
    __syncthreads();
    const float4* zv = (const float4*)zs;
    #pragma unroll
    for (int rr = 0; rr < 4; rr++) {
        const int i = h * 64 + wid + rr * 16;
        const float4* row = (const float4*)(Wv + (size_t)i * Dd);
        float s = 0.f;
        #pragma unroll
        for (int k = 0; k < 4; k++) s += dot4(row[lane + 32 * k], zv[lane + 32 * k]);
        s = warp_sum(s);
        if (lane == 0) g_w[b][i] = s + bv[i];
    }
}

// ============ k_wo: warp = (row, batch). grid 256, 256 thr ============
__global__ void k_wo(const float* __restrict__ Wo, const float* __restrict__ bo,
                     const float* __restrict__ ct) {
    __shared__ __align__(16) float4 ws4[Bx * 128];   // 8 KB
    const int t = threadIdx.x, wid = t >> 5, lane = t & 31;
    {
        const float4* gw4 = (const float4*)&g_w[0][0];
        ws4[t] = gw4[t];
        ws4[t + 256] = gw4[t + 256];
    }
    __syncthreads();
    const int gw = blockIdx.x * 8 + wid;
    const int r = gw >> 2, b = gw & 3;
    const float4* row = (const float4*)(Wo + (size_t)r * Dd);
    float s = 0.f;
    #pragma unroll
    for (int k = 0; k < 4; k++) s += dot4(row[lane + 32 * k], ws4[b * 128 + lane + 32 * k]);
    s = warp_sum(s);
    if (lane == 0) g_y[b][r] = s + bo[r] + ct[r];
}

// ============ k_ln: LayerNorm CLS row. grid Bx, 512 thr ============
__global__ void k_ln(const float* __restrict__ gamma, const float* __restrict__ beta,
                     float* __restrict__ out) {
    const int b = blockIdx.x, t = threadIdx.x;
    __shared__ float red[512];
    const float y = g_y[b][t];
    red[t] = y; __syncthreads();
    for (int o = 256; o; o >>= 1) { if (t < o) red[t] += red[t + o]; __syncthreads(); }
    const float mu = red[0] * (1.f / Dd);
    __syncthreads();
    const float dy = y - mu;
    red[t] = dy * dy; __syncthreads();
    for (int o = 256; o; o >>= 1) { if (t < o) red[t] += red[t + o]; __syncthreads(); }
    const float rs = rsqrtf(red[0] * (1.f / Dd) + 1e-5f);
    out[(size_t)b * Dd + t] = dy * rs * gamma[t] + beta[t];
}

// ---------------- launcher ----------------
extern "C" void kernel_launch(void* const* d_in, const int* in_sizes, int n_in,
                              void* d_out, int out_size) {
    const float* nf    = (const float*)d_in[0];
    // d_in[1] edge_weights, d_in[2] adj_matrix: dead for CLS-row output
    const float* masks = (const float*)d_in[3];
    const float* ct    = (const float*)d_in[4];
    const float* Wq    = (const float*)d_in[5];
    const float* bq    = (const float*)d_in[6];
    const float* Wk    = (const float*)d_in[7];
    const float* bk    = (const float*)d_in[8];
    const float* Wv    = (const float*)d_in[9];
    const float* bv    = (const float*)d_in[10];
    const float* Wo    = (const float*)d_in[11];
    const float* bo    = (const float*)d_in[12];
    const float* gamma = (const float*)d_in[13];
    const float* beta  = (const float*)d_in[14];
    float* out = (float*)d_out;

    k_prep   <<<dim3(Hh, 8), 512>>>(Wq, bq, Wk, bk, ct);
    k_scores <<<dim3(Nn / 8, Bx), 256>>>(nf, masks);
    k_softmax<<<32, 1024>>>();
    k_z      <<<dim3(ZCH, Bx), 512>>>(nf);
    k_zv     <<<dim3(Hh, Bx), 512>>>(ct, Wv, bv);
    k_wo     <<<256, 256>>>(Wo, bo, ct);
    k_ln     <<<Bx, 512>>>(gamma, beta, out);
}

// round 7
// speedup vs baseline: 1.0788x; 1.0077x over previous
#include <cuda_runtime.h>

#define Bx 4
#define Nn 2048
#define Dd 512
#define Hh 8
#define ZCH 128    // z chunks
#define ZR  16     // rows per z chunk

// ---------------- device scratch ----------------
__device__ float g_u[Hh][Dd];
__device__ float g_ch[Hh];
__device__ float g_s0p[Hh][8];
__device__ float g_sc[Bx][Hh][Nn];         // node scores (node = j-1)
__device__ float g_nm[Bx][Hh];             // softmax max
__device__ float g_nrs[Bx][Hh];            // softmax 1/sum
__device__ float g_zp[ZCH][Bx][Hh][Dd];    // final-p-weighted z partials
__device__ float g_w[Bx][Dd];
__device__ float g_y[Bx][Dd];

__device__ __forceinline__ float warp_sum(float v) {
    #pragma unroll
    for (int o = 16; o; o >>= 1) v += __shfl_xor_sync(0xffffffffu, v, o);
    return v;
}
__device__ __forceinline__ float warp_max(float v) {
    #pragma unroll
    for (int o = 16; o; o >>= 1) v = fmaxf(v, __shfl_xor_sync(0xffffffffu, v, o));
    return v;
}
__device__ __forceinline__ float dot4(float4 a, float4 b) {
    return a.x * b.x + a.y * b.y + a.z * b.z + a.w * b.w;
}

// ============ k_prep: per (head, d-chunk): q0 slice, u, s0 partials, ch ============
// grid (Hh, 8), 512 threads
__global__ void k_prep(const float* __restrict__ Wq, const float* __restrict__ bq,
                       const float* __restrict__ Wk, const float* __restrict__ bk,
                       const float* __restrict__ ct) {
    const int h = blockIdx.x, dc = blockIdx.y;
    const int t = threadIdx.x, wid = t >> 5, lane = t & 31;
    __shared__ __align__(16) float cts[Dd];
    __shared__ float q0s[64], red8[8][64], red64[64];
    cts[t] = ct[t];
    __syncthreads();
    {   // q0 slice for head h: 16 warps x 4 rows
        const float4* cv = (const float4*)cts;
        #pragma unroll
        for (int rr = 0; rr < 4; rr++) {
            const int i = wid + rr * 16;
            const float4* row = (const float4*)(Wq + (size_t)(h * 64 + i) * Dd);
            float s = 0.f;
            #pragma unroll
            for (int k = 0; k < 4; k++) s += dot4(row[lane + 32 * k], cv[lane + 32 * k]);
            s = warp_sum(s);
            if (lane == 0) q0s[i] = s + bq[h * 64 + i];
        }
    }
    __syncthreads();
    const int part8 = t >> 6, dl = t & 63;
    {
        const float* base = Wk + (size_t)(h * 64 + part8 * 8) * Dd + dc * 64 + dl;
        float acc = 0.f;
        #pragma unroll
        for (int i = 0; i < 8; i++) acc += q0s[part8 * 8 + i] * base[(size_t)i * Dd];
        red8[part8][dl] = acc;
    }
    __syncthreads();
    if (t < 64) {
        float u = 0.f;
        #pragma unroll
        for (int p = 0; p < 8; p++) u += red8[p][t];
        g_u[h][dc * 64 + t] = u;
        red64[t] = u * cts[dc * 64 + t];
    }
    __syncthreads();
    if (t < 32) {
        float v = red64[t] + red64[t + 32];
        v = warp_sum(v);
        if (t == 0) g_s0p[h][dc] = v;
        if (dc == 0) {
            float cvv = q0s[t] * bk[h * 64 + t] + q0s[t + 32] * bk[h * 64 + t + 32];
            cvv = warp_sum(cvv);
            if (t == 0) g_ch[h] = cvv;
        }
    }
}

// ============ k_scores: warp = 2 node rows (MLP 8), all 8 heads ============
// grid (Nn/16, Bx), 256 threads
__global__ void k_scores(const float* __restrict__ nf, const float* __restrict__ masks) {
    __shared__ __align__(16) float4 us4[Hh * 128];   // 16 KB
    __shared__ float chs[Hh];
    const int b = blockIdx.y;
    const int t = threadIdx.x, wid = t >> 5, lane = t & 31;
    {
        const float4* uf = (const float4*)&g_u[0][0];
        #pragma unroll
        for (int k = 0; k < 4; k++) us4[t + k * 256] = uf[t + k * 256];
        if (t < Hh) chs[t] = g_ch[t];
    }
    __syncthreads();
    const int n0 = blockIdx.x * 16 + wid * 2;
    const float4* x4 = (const float4*)(nf + ((size_t)b * Nn + n0) * Dd);
    float4 xr0[4], xr1[4];
    #pragma unroll
    for (int k = 0; k < 4; k++) { xr0[k] = x4[lane + 32 * k]; xr1[k] = x4[128 + lane + 32 * k]; }
    const float mv0 = masks[(size_t)b * Nn + n0];
    const float mv1 = masks[(size_t)b * Nn + n0 + 1];
    #pragma unroll
    for (int h = 0; h < Hh; h++) {
        float s0 = 0.f, s1 = 0.f;
        #pragma unroll
        for (int k = 0; k < 4; k++) {
            const float4 uv = us4[h * 128 + lane + 32 * k];
            s0 += dot4(uv, xr0[k]);
            s1 += dot4(uv, xr1[k]);
        }
        s0 = warp_sum(s0);
        s1 = warp_sum(s1);
        if (lane == 0) {
            float v0 = (s0 + chs[h]) * 0.125f;
            float v1 = (s1 + chs[h]) * 0.125f;
            if (mv0 * mv0 == 0.f) v0 = -1e9f;
            if (mv1 * mv1 == 0.f) v1 = -1e9f;
            g_sc[b][h][n0] = v0;
            g_sc[b][h][n0 + 1] = v1;
        }
    }
}

// ============ k_softmax: per (b,h) -> (M, 1/S). grid 32, 1024 thr ============
__global__ void k_softmax() {
    const int b = blockIdx.x >> 3, h = blockIdx.x & 7;
    const int t = threadIdx.x, wid = t >> 5, lane = t & 31;
    __shared__ float red[32];
    __shared__ float Msh, s0sh;
    const float v0 = g_sc[b][h][t], v1 = g_sc[b][h][t + 1024];
    float m = warp_max(fmaxf(v0, v1));
    if (lane == 0) red[wid] = m;
    __syncthreads();
    if (wid == 0) {
        float x = warp_max(red[lane]);
        if (lane == 0) {
            float sp = 0.f;
            #pragma unroll
            for (int dc = 0; dc < 8; dc++) sp += g_s0p[h][dc];
            const float s0 = (sp + g_ch[h]) * 0.125f;
            s0sh = s0;
            Msh = fmaxf(x, s0);
        }
    }
    __syncthreads();
    const float M = Msh;
    float e = expf(v0 - M) + expf(v1 - M);
    e = warp_sum(e);
    if (lane == 0) red[wid] = e;
    __syncthreads();
    if (wid == 0) {
        float x = warp_sum(red[lane]);
        if (lane == 0) {
            g_nm[b][h] = M;
            g_nrs[b][h] = 1.f / (x + expf(s0sh - M));
        }
    }
}

// ============ k_z: final-p-weighted partials; 16 rows, float2 dims ============
// grid (ZCH, Bx), 256 threads
__global__ void k_z(const float* __restrict__ nf) {
    const int c = blockIdx.x, b = blockIdx.y;
    const int t = threadIdx.x;
    __shared__ float ps[Hh][ZR];
    if (t < Hh * ZR) {
        const int h = t >> 4, jj = t & 15;
        ps[h][jj] = expf(g_sc[b][h][c * ZR + jj] - g_nm[b][h]) * g_nrs[b][h];
    }
    __syncthreads();
    float2 acc[Hh];
    #pragma unroll
    for (int h = 0; h < Hh; h++) acc[h] = make_float2(0.f, 0.f);
    const float2* xp = (const float2*)(nf + ((size_t)b * Nn + c * ZR) * Dd) + t;
    #pragma unroll
    for (int jj = 0; jj < ZR; jj++) {
        const float2 xv = xp[jj * 256];
        #pragma unroll
        for (int h = 0; h < Hh; h++) {
            const float p = ps[h][jj];
            acc[h].x += p * xv.x;
            acc[h].y += p * xv.y;
        }
    }
    #pragma unroll
    for (int h = 0; h < Hh; h++)
        ((float2*)&g_zp[c][b][h][0])[t] = acc[h];
}

// ============ k_zv: sum chunk partials + CLS term + Wv GEMV ============
// grid (Hh, Bx), 512 threads
__global__ void k_zv(const float* __restrict__ ct, const float* __restrict__ Wv,
                     const float* __restrict__ bv) {
    const int h = blockIdx.x, b = blockIdx.y;
    const int t = threadIdx.x, wid = t >> 5, lane = t & 31;
    __shared__ __align__(16) float zs[Dd];
    __shared__ float p0sh;
    if (t == 0) {
        float sp = 0.f;
        #pragma unroll
        for (int dc = 0; dc < 8; dc++) sp += g_s0p[h][dc];
        const float s0 = (sp + g_ch[h]) * 0.125f;
        p0sh = expf(s0 - g_nm[b][h]) * g_nrs[b][h];
    }
    __syncthreads();
    {
        float acc = p0sh * ct[t];
        #pragma unroll 8
        for (int c = 0; c < ZCH; c++) acc += g_zp[c][b][h][t];
        zs[t] = acc;
    }
    __syncthreads();
    const float4* zv = (const float4*)zs;
    #pragma unroll
    for (int rr = 0; rr < 4; rr++) {
        const int i = h * 64 + wid + rr * 16;
        const float4* row = (const float4*)(Wv + (size_t)i * Dd);
        float s = 0.f;
        #pragma unroll
        for (int k = 0; k < 4; k++) s += dot4(row[lane + 32 * k], zv[lane + 32 * k]);
        s = warp_sum(s);
        if (lane == 0) g_w[b][i] = s + bv[i];
    }
}

// ============ k_wo: warp = (row, batch). grid 256, 256 thr ============
__global__ void k_wo(const float* __restrict__ Wo, const float* __restrict__ bo,
                     const float* __restrict__ ct) {
    __shared__ __align__(16) float4 ws4[Bx * 128];   // 8 KB
    const int t = threadIdx.x, wid = t >> 5, lane = t & 31;
    {
        const float4* gw4 = (const float4*)&g_w[0][0];
        ws4[t] = gw4[t];
        ws4[t + 256] = gw4[t + 256];
    }
    __syncthreads();
    const int gw = blockIdx.x * 8 + wid;
    const int r = gw >> 2, b = gw & 3;
    const float4* row = (const float4*)(Wo + (size_t)r * Dd);
    float s = 0.f;
    #pragma unroll
    for (int k = 0; k < 4; k++) s += dot4(row[lane + 32 * k], ws4[b * 128 + lane + 32 * k]);
    s = warp_sum(s);
    if (lane == 0) g_y[b][r] = s + bo[r] + ct[r];
}

// ============ k_ln: LayerNorm CLS row. grid Bx, 512 thr ============
__global__ void k_ln(const float* __restrict__ gamma, const float* __restrict__ beta,
                     float* __restrict__ out) {
    const int b = blockIdx.x, t = threadIdx.x;
    __shared__ float red[512];
    const float y = g_y[b][t];
    red[t] = y; __syncthreads();
    for (int o = 256; o; o >>= 1) { if (t < o) red[t] += red[t + o]; __syncthreads(); }
    const float mu = red[0] * (1.f / Dd);
    __syncthreads();
    const float dy = y - mu;
    red[t] = dy * dy; __syncthreads();
    for (int o = 256; o; o >>= 1) { if (t < o) red[t] += red[t + o]; __syncthreads(); }
    const float rs = rsqrtf(red[0] * (1.f / Dd) + 1e-5f);
    out[(size_t)b * Dd + t] = dy * rs * gamma[t] + beta[t];
}

// ---------------- launcher ----------------
extern "C" void kernel_launch(void* const* d_in, const int* in_sizes, int n_in,
                              void* d_out, int out_size) {
    const float* nf    = (const float*)d_in[0];
    // d_in[1] edge_weights, d_in[2] adj_matrix: dead for CLS-row output
    const float* masks = (const float*)d_in[3];
    const float* ct    = (const float*)d_in[4];
    const float* Wq    = (const float*)d_in[5];
    const float* bq    = (const float*)d_in[6];
    const float* Wk    = (const float*)d_in[7];
    const float* bk    = (const float*)d_in[8];
    const float* Wv    = (const float*)d_in[9];
    const float* bv    = (const float*)d_in[10];
    const float* Wo    = (const float*)d_in[11];
    const float* bo    = (const float*)d_in[12];
    const float* gamma = (const float*)d_in[13];
    const float* beta  = (const float*)d_in[14];
    float* out = (float*)d_out;

    k_prep   <<<dim3(Hh, 8), 512>>>(Wq, bq, Wk, bk, ct);
    k_scores <<<dim3(Nn / 16, Bx), 256>>>(nf, masks);
    k_softmax<<<32, 1024>>>();
    k_z      <<<dim3(ZCH, Bx), 256>>>(nf);
    k_zv     <<<dim3(Hh, Bx), 512>>>(ct, Wv, bv);
    k_wo     <<<256, 256>>>(Wo, bo, ct);
    k_ln     <<<Bx, 512>>>(gamma, beta, out);
}